// round 3
// baseline (speedup 1.0000x reference)
#include <cuda_runtime.h>
#include <cstdint>

// AggregateLevels: FPN anchor generation + delta decode, 5 levels fused.
// Shapes fixed by the dataset: B=16, IH=IW=1024.
// Levels i=2..6: h=w = 256,128,64,32,16 ; hw = 65536,16384,4096,1024,256.
// Per-level positions 3*hw: 196608,49152,12288,3072,768 -> total A = 261888.
// Output layout in d_out (float32), concatenated:
//   scores  [B, A, 2]  at offset 0
//   boxes   [B, A, 4]  at offset B*A*2
//   anchors [B, A, 4]  at offset B*A*6

#define B_SZ   16
#define A_TOT  261888

__constant__ int   c_off[5]   = {0, 196608, 245760, 258048, 261120};
__constant__ int   c_lghw[5]  = {16, 14, 12, 10, 8};
__constant__ int   c_lgw[5]   = {8, 7, 6, 5, 4};
__constant__ float c_scale[5] = {4.f, 8.f, 16.f, 32.f, 64.f};
__constant__ float c_half[5]  = {1.5f, 3.5f, 7.5f, 15.5f, 31.5f};
__constant__ float c_anch[5]  = {0.0625f, 0.125f, 0.25f, 0.5f, 1.0f}; // 2^(i-6)

struct Ptrs {
    const float* cs[5];
    const float* bp[5];
    const int*   ih;
    const int*   iw;
};

__global__ __launch_bounds__(256)
void aggregate_levels_kernel(Ptrs ptrs, float* __restrict__ out) {
    const int p = blockIdx.x * 256 + threadIdx.x;   // anchor position, < A_TOT
    const int b = blockIdx.y;                       // batch

    // level decode: 4 compares
    const int l = (p >= 196608) + (p >= 245760) + (p >= 258048) + (p >= 261120);

    const int q     = p - c_off[l];
    const int lghw  = c_lghw[l];
    const int hw    = 1 << lghw;
    const int a     = q >> lghw;          // aspect index 0..2
    const int rem   = q & (hw - 1);       // y*w + x
    const int lgw   = c_lgw[l];
    const int y     = rem >> lgw;
    const int x     = rem & ((1 << lgw) - 1);

    const float fih = (float)(*ptrs.ih);
    const float fiw = (float)(*ptrs.iw);

    const float s    = c_scale[l];
    const float half = c_half[l];
    const float a_cy = s * (float)y + half;
    const float a_cx = s * (float)x + half;
    const float ha   = fih * c_anch[l];
    const float wa   = fiw * c_anch[l];
    const float a_h  = (a == 2) ? 2.0f * ha : ha;   // hs = {ha, ha, 2ha}
    const float a_w  = (a == 0) ? 2.0f * wa : wa;   // ws = {2wa, wa, wa}

    // class scores: planes (a*2 + c) for c in {0,1}
    const float* cs = ptrs.cs[l] + (((b * 6 + a * 2) << lghw) + rem);
    const float c0 = __ldg(cs);
    const float c1 = __ldg(cs + hw);

    // bbox deltas: planes (a*4 + d) for d in 0..3
    const float* bp = ptrs.bp[l] + (((b * 12 + a * 4) << lghw) + rem);
    const float d0 = __ldg(bp);
    const float d1 = __ldg(bp + hw);
    const float d2 = __ldg(bp + 2 * hw);
    const float d3 = __ldg(bp + 3 * hw);

    const float cyc = a_cy + d0 * a_h;
    const float cxc = a_cx + d1 * a_w;
    const float hh  = a_h * __expf(d2) ;
    const float ww  = a_w * __expf(d3);

    const float y1 = fminf(fmaxf(cyc - 0.5f * hh, 0.0f), fih);
    const float x1 = fminf(fmaxf(cxc - 0.5f * ww, 0.0f), fiw);
    const float y2 = fminf(fmaxf(cyc + 0.5f * hh, 0.0f), fih);
    const float x2 = fminf(fmaxf(cxc + 0.5f * ww, 0.0f), fiw);

    const size_t idx = (size_t)b * A_TOT + p;

    // scores as float2 (8B coalesced)
    float2* os = reinterpret_cast<float2*>(out);
    os[idx] = make_float2(c0, c1);

    // boxes as float4 (16B coalesced); base offset B*A*2 floats (16B aligned)
    float4* ob = reinterpret_cast<float4*>(out + (size_t)B_SZ * A_TOT * 2);
    ob[idx] = make_float4(y1, x1, y2, x2);

    // anchors as float4; base offset B*A*6 floats (16B aligned)
    float4* oa = reinterpret_cast<float4*>(out + (size_t)B_SZ * A_TOT * 6);
    oa[idx] = make_float4(a_cy, a_cx, a_h, a_w);
}

extern "C" void kernel_launch(void* const* d_in, const int* in_sizes, int n_in,
                              void* d_out, int out_size) {
    (void)out_size;
    // Identify inputs by element count (robust to metadata ordering).
    // Level l=0..4 (FPN i=l+2): hw = 65536>>(2*l); cs has 16*6*hw elems,
    // bp has 16*12*hw elems. All 10 counts are distinct. Scalars have size 1
    // (dict order: img_h then img_w).
    Ptrs ptrs;
    ptrs.ih = nullptr; ptrs.iw = nullptr;
    for (int i = 0; i < n_in; ++i) {
        const long long sz = in_sizes[i];
        if (sz == 1) {
            if (!ptrs.ih) ptrs.ih = (const int*)d_in[i];
            else          ptrs.iw = (const int*)d_in[i];
            continue;
        }
        for (int l = 0; l < 5; ++l) {
            const long long hw = 65536LL >> (2 * l);
            if (sz == 16LL * 6 * hw)  ptrs.cs[l] = (const float*)d_in[i];
            if (sz == 16LL * 12 * hw) ptrs.bp[l] = (const float*)d_in[i];
        }
    }

    dim3 grid(A_TOT / 256, B_SZ);   // 261888 = 1023 * 256 exactly
    aggregate_levels_kernel<<<grid, 256>>>(ptrs, (float*)d_out);
}